// round 16
// baseline (speedup 1.0000x reference)
#include <cuda_runtime.h>
#include <cuda_bf16.h>

#define D 128

__global__ __launch_bounds__(512) void arccos_hess_kernel(
    const float* __restrict__ z1,
    const float* __restrict__ z2,
    float* __restrict__ out,
    int B)
{
    // grid = 6*B, 512 threads. Each CTA writes HALF of one matrix (64 rows =
    // 32KB) -> preamble-per-byte identical to the best-known half-split, but
    // T_CTA halves (finer scheduling tail, no extra preamble recompute).
    // Ordering: m-major, then b, then half (LSB) -> contiguous write window.
    int bid  = blockIdx.x;
    int B2   = 2 * B;
    int m    = bid >= 2 * B2 ? 2 : (bid >= B2 ? 1 : 0);
    int sub  = bid - m * B2;
    int b    = sub >> 1;
    int half = sub & 1;          // rows [half*64, half*64+64)

    __shared__ float a[D];   // z1 unit vector
    __shared__ float v[D];   // z2 unit vector
    __shared__ float part[3][4];

    int tid  = threadIdx.x;
    int wid  = tid >> 5;
    int lane = tid & 31;

    float x1 = 0.f, x2 = 0.f;
    if (tid < D) {
        x1 = z1[(size_t)b * D + tid];
        x2 = z2[(size_t)b * D + tid];
    }

    // Warp reduction (warps 0-3 carry data; others contribute zeros locally).
    float p11 = x1 * x1, p22 = x2 * x2, p12 = x1 * x2;
    #pragma unroll
    for (int o = 16; o; o >>= 1) {
        p11 += __shfl_down_sync(0xffffffffu, p11, o);
        p22 += __shfl_down_sync(0xffffffffu, p22, o);
        p12 += __shfl_down_sync(0xffffffffu, p12, o);
    }
    if (lane == 0 && wid < 4) {
        part[0][wid] = p11;
        part[1][wid] = p22;
        part[2][wid] = p12;
    }
    __syncthreads();

    // Every thread finishes the reduction itself (broadcast LDS).
    float s11 = 0.f, s22 = 0.f, s12 = 0.f;
    #pragma unroll
    for (int w = 0; w < 4; w++) {
        s11 += part[0][w];
        s22 += part[1][w];
        s12 += part[2][w];
    }
    float rn1 = rsqrtf(s11);
    float rn2 = rsqrtf(s22);
    float c   = s12 * rn1 * rn2;
    float c3  = 3.0f * c;
    float scale = (m == 0) ? rn1 * rn1 : (m == 1) ? rn1 * rn2 : rn2 * rn2;

    if (tid < D) {
        a[tid] = x1 * rn1;
        v[tid] = x2 * rn2;
    }
    __syncthreads();

    size_t mstride = (size_t)B * D * D;
    float* o_m = out + (size_t)m * mstride + (size_t)b * D * D;

    // 512 threads over 64 rows x 32 quads = 2048 quads -> 4 iterations.
    // j-quad fixed per thread; i advances by 16 rows per iteration.
    int i0 = (half << 6) + (tid >> 5);   // base row: half*64 + 0..15
    int j  = (tid & 31) << 2;            // 0..124 step 4 (fixed)

    float4 aj = *reinterpret_cast<const float4*>(&a[j]);
    float4 vj = *reinterpret_cast<const float4*>(&v[j]);
    const float* paj = &aj.x;
    const float* pvj = &vj.x;

    float* row = o_m + (size_t)i0 * D + j;

    if (m == 1) {
        // H12 = (-I + a a^T + v v^T - c * v a^T) * scale
        #pragma unroll
        for (int it = 0; it < 4; it++) {
            int i = i0 + it * 16;
            float ai = a[i];
            float vi = v[i];
            float4 h; float* ph = &h.x;
            int d = i - j;
            #pragma unroll
            for (int k = 0; k < 4; k++) {
                float ajk = paj[k], vjk = pvj[k];
                float e = (d == k) ? -1.f : 0.f;
                ph[k] = (e + ai * ajk + vi * vjk - c * vi * ajk) * scale;
            }
            __stcs(reinterpret_cast<float4*>(row), h);
            row += 16 * D;
        }
    } else {
        // H11/H22 = (c*I + a v^T + v a^T - 3c * u u^T) * scale, u = a or v.
        float4 uj;
        uj.x = (m == 0) ? paj[0] : pvj[0];
        uj.y = (m == 0) ? paj[1] : pvj[1];
        uj.z = (m == 0) ? paj[2] : pvj[2];
        uj.w = (m == 0) ? paj[3] : pvj[3];
        const float* puj = &uj.x;

        #pragma unroll
        for (int it = 0; it < 4; it++) {
            int i = i0 + it * 16;
            float ai = a[i];
            float vi = v[i];
            float ui3 = c3 * ((m == 0) ? ai : vi);
            float4 h; float* ph = &h.x;
            int d = i - j;
            #pragma unroll
            for (int k = 0; k < 4; k++) {
                float e = (d == k) ? c : 0.f;
                ph[k] = (e + ai * pvj[k] + vi * paj[k] - ui3 * puj[k]) * scale;
            }
            __stcs(reinterpret_cast<float4*>(row), h);
            row += 16 * D;
        }
    }
}

extern "C" void kernel_launch(void* const* d_in, const int* in_sizes, int n_in,
                              void* d_out, int out_size) {
    const float* z1 = (const float*)d_in[0];
    const float* z2 = (const float*)d_in[1];
    float* out = (float*)d_out;
    int B = in_sizes[0] / D;   // 4096
    arccos_hess_kernel<<<6 * B, 512>>>(z1, z2, out, B);
}

// round 17
// speedup vs baseline: 1.1012x; 1.1012x over previous
#include <cuda_runtime.h>
#include <cuda_bf16.h>

#define D 128

__global__ __launch_bounds__(256) void arccos_hess_kernel(
    const float* __restrict__ z1,
    const float* __restrict__ z2,
    float* __restrict__ out,
    int B)
{
    // grid = 6*B. Each CTA writes HALF of one matrix (64 rows = 32KB) so the
    // scheduling tail is twice as fine. Ordering: m-major, then b, then half
    // (LSB) -> resident CTAs still form one contiguous DRAM write window.
    int bid  = blockIdx.x;
    int B2   = 2 * B;
    int m    = bid >= 2 * B2 ? 2 : (bid >= B2 ? 1 : 0);
    int sub  = bid - m * B2;
    int b    = sub >> 1;
    int half = sub & 1;          // 0: rows 0..63, 1: rows 64..127

    __shared__ float a[D];   // z1 unit vector
    __shared__ float v[D];   // z2 unit vector
    __shared__ float part[3][8];

    int tid  = threadIdx.x;
    int wid  = tid >> 5;
    int lane = tid & 31;

    float x1 = 0.f, x2 = 0.f;
    if (tid < D) {
        x1 = z1[(size_t)b * D + tid];
        x2 = z2[(size_t)b * D + tid];
    }

    // Warp reduction of s11, s22, s12.
    float p11 = x1 * x1, p22 = x2 * x2, p12 = x1 * x2;
    #pragma unroll
    for (int o = 16; o; o >>= 1) {
        p11 += __shfl_down_sync(0xffffffffu, p11, o);
        p22 += __shfl_down_sync(0xffffffffu, p22, o);
        p12 += __shfl_down_sync(0xffffffffu, p12, o);
    }
    if (lane == 0) { part[0][wid] = p11; part[1][wid] = p22; part[2][wid] = p12; }
    __syncthreads();

    // Every thread finishes the reduction itself (broadcast LDS).
    float s11 = 0.f, s22 = 0.f, s12 = 0.f;
    #pragma unroll
    for (int w = 0; w < 8; w++) {
        s11 += part[0][w];
        s22 += part[1][w];
        s12 += part[2][w];
    }
    float rn1 = rsqrtf(s11);
    float rn2 = rsqrtf(s22);
    float c   = s12 * rn1 * rn2;
    float c3  = 3.0f * c;
    float scale = (m == 0) ? rn1 * rn1 : (m == 1) ? rn1 * rn2 : rn2 * rn2;

    if (tid < D) {
        a[tid] = x1 * rn1;
        v[tid] = x2 * rn2;
    }
    __syncthreads();

    size_t mstride = (size_t)B * D * D;
    float* o_m = out + (size_t)m * mstride + (size_t)b * D * D;

    // Per-thread: j-quad fixed; i covers 8 rows spaced by 8, within this half.
    int i0 = (half << 6) + (tid >> 5);   // base row: 0..7 or 64..71
    int j  = (tid & 31) << 2;            // 0..124 step 4 (fixed)

    float4 aj = *reinterpret_cast<const float4*>(&a[j]);
    float4 vj = *reinterpret_cast<const float4*>(&v[j]);
    const float* paj = &aj.x;
    const float* pvj = &vj.x;

    float* row = o_m + (size_t)i0 * D + j;

    if (m == 1) {
        // H12 = (-I + a a^T + v v^T - c * v a^T) * scale
        #pragma unroll
        for (int it = 0; it < 8; it++) {
            int i = i0 + it * 8;
            float ai = a[i];
            float vi = v[i];
            float4 h; float* ph = &h.x;
            int d = i - j;
            #pragma unroll
            for (int k = 0; k < 4; k++) {
                float ajk = paj[k], vjk = pvj[k];
                float e = (d == k) ? -1.f : 0.f;
                ph[k] = (e + ai * ajk + vi * vjk - c * vi * ajk) * scale;
            }
            __stcs(reinterpret_cast<float4*>(row), h);
            row += 8 * D;
        }
    } else {
        // H11/H22 = (c*I + a v^T + v a^T - 3c * u u^T) * scale, u = a or v.
        float4 uj;
        uj.x = (m == 0) ? paj[0] : pvj[0];
        uj.y = (m == 0) ? paj[1] : pvj[1];
        uj.z = (m == 0) ? paj[2] : pvj[2];
        uj.w = (m == 0) ? paj[3] : pvj[3];
        const float* puj = &uj.x;

        #pragma unroll
        for (int it = 0; it < 8; it++) {
            int i = i0 + it * 8;
            float ai = a[i];
            float vi = v[i];
            float ui3 = c3 * ((m == 0) ? ai : vi);
            float4 h; float* ph = &h.x;
            int d = i - j;
            #pragma unroll
            for (int k = 0; k < 4; k++) {
                float e = (d == k) ? c : 0.f;
                ph[k] = (e + ai * pvj[k] + vi * paj[k] - ui3 * puj[k]) * scale;
            }
            __stcs(reinterpret_cast<float4*>(row), h);
            row += 8 * D;
        }
    }
}

extern "C" void kernel_launch(void* const* d_in, const int* in_sizes, int n_in,
                              void* d_out, int out_size) {
    const float* z1 = (const float*)d_in[0];
    const float* z2 = (const float*)d_in[1];
    float* out = (float*)d_out;
    int B = in_sizes[0] / D;   // 4096
    arccos_hess_kernel<<<6 * B, 256>>>(z1, z2, out, B);
}